// round 3
// baseline (speedup 1.0000x reference)
#include <cuda_runtime.h>

#define D     64
#define NMEM  16
#define NHOP  2

// Block: 128 threads (4 warps). One block per batch element.
// Warp w handles slots m = 4*w .. 4*w+3.
__global__ __launch_bounds__(128, 8)
void ripple_kernel(const int* __restrict__ items,
                   const int* __restrict__ mem_h,
                   const int* __restrict__ mem_r,
                   const int* __restrict__ mem_t,
                   const float* __restrict__ entity,
                   const float* __restrict__ rel,
                   const float* __restrict__ W,
                   float* __restrict__ out,
                   int B)
{
    const int b    = blockIdx.x;
    const int tid  = threadIdx.x;
    const int lane = tid & 31;
    const int warp = tid >> 5;

    __shared__ float item_s[D];
    __shared__ float y_s[D];
    __shared__ float o_s[D];
    __shared__ float logits_s[NMEM];
    __shared__ float probs_s[NMEM];

    // load item embedding
    if (tid < D) {
        item_s[tid] = entity[(size_t)items[b] * D + tid];
        y_s[tid]    = 0.0f;
    }
    __syncthreads();

    for (int hop = 0; hop < NHOP; ++hop) {
        const int slot_base = hop * B * NMEM + b * NMEM;

        // ---- logits[m] = item^T * R_m * h_m ----
        // compute u_j = sum_i item[i] * R[i][j]  (coalesced over j = lane, lane+32)
        // then logits = sum_j u_j * h[j]
        #pragma unroll
        for (int s = 0; s < 4; ++s) {
            const int m    = warp * 4 + s;
            const int hidx = mem_h[slot_base + m];
            const int ridx = mem_r[slot_base + m];
            const float* __restrict__ R = rel    + (size_t)ridx * (D * D);
            const float* __restrict__ H = entity + (size_t)hidx * D;

            float u0 = 0.0f, u1 = 0.0f;
            #pragma unroll
            for (int i = 0; i < D; ++i) {
                const float it = item_s[i];
                u0 = fmaf(it, R[i * D + lane],      u0);
                u1 = fmaf(it, R[i * D + lane + 32], u1);
            }
            float lg = u0 * H[lane] + u1 * H[lane + 32];
            #pragma unroll
            for (int off = 16; off > 0; off >>= 1)
                lg += __shfl_xor_sync(0xffffffffu, lg, off);
            if (lane == 0) logits_s[m] = lg;
        }
        __syncthreads();

        // ---- softmax numerator (max-subtracted) ----
        if (tid < NMEM) {
            float mx = logits_s[0];
            #pragma unroll
            for (int k = 1; k < NMEM; ++k) mx = fmaxf(mx, logits_s[k]);
            probs_s[tid] = expf(logits_s[tid] - mx);
        }
        __syncthreads();

        // ---- o = softmax(logits) . t   (threads 0..63 each own one dim) ----
        if (tid < D) {
            float denom = 0.0f;
            #pragma unroll
            for (int m = 0; m < NMEM; ++m) denom += probs_s[m];
            float o = 0.0f;
            #pragma unroll
            for (int m = 0; m < NMEM; ++m) {
                const int tix = mem_t[slot_base + m];
                o = fmaf(probs_s[m], entity[(size_t)tix * D + tid], o);
            }
            o /= denom;
            y_s[tid] += o;
            o_s[tid]  = o + item_s[tid];   // v = item + o, staged for transform
        }
        __syncthreads();

        // ---- item = W @ v   (v in o_s; item_s not read, safe to overwrite) ----
        if (tid < D) {
            float acc = 0.0f;
            #pragma unroll
            for (int j = 0; j < D; ++j)
                acc = fmaf(W[tid * D + j], o_s[j], acc);
            item_s[tid] = acc;
        }
        __syncthreads();
    }

    // ---- score = dot(item_final, y) ---- (warp 0 reduces)
    if (warp == 0) {
        float v = item_s[lane] * y_s[lane] + item_s[lane + 32] * y_s[lane + 32];
        #pragma unroll
        for (int off = 16; off > 0; off >>= 1)
            v += __shfl_xor_sync(0xffffffffu, v, off);
        if (lane == 0) out[b] = v;
    }
}

extern "C" void kernel_launch(void* const* d_in, const int* in_sizes, int n_in,
                              void* d_out, int out_size)
{
    const int*   items  = (const int*)  d_in[0];
    const int*   mem_h  = (const int*)  d_in[1];
    const int*   mem_r  = (const int*)  d_in[2];
    const int*   mem_t  = (const int*)  d_in[3];
    const float* entity = (const float*)d_in[4];
    const float* rel    = (const float*)d_in[5];
    const float* W      = (const float*)d_in[6];
    float*       out    = (float*)d_out;

    const int B = in_sizes[0];   // 4096

    ripple_kernel<<<B, 128>>>(items, mem_h, mem_r, mem_t, entity, rel, W, out, B);
}

// round 4
// speedup vs baseline: 1.1883x; 1.1883x over previous
#include <cuda_runtime.h>

#define D     64
#define NMEM  16
#define NHOP  2
#define NREL  200
#define BMAX  4096
#define SMAX  (BMAX * NMEM)     // 65536 slots per hop
#define TILE  64                // slots per GEMM tile
#define PAD   72                // row stride (floats): 288B -> float4 aligned every row

// ---- persistent scratch (no allocation allowed) ----
__device__ int   g_count [NHOP][NREL];
__device__ int   g_cursor[NHOP][NREL];
__device__ int   g_off   [NHOP][NREL + 1];
__device__ int   g_slots [NHOP][SMAX];     // slot ids grouped by relation
__device__ float g_logits[NHOP][SMAX];
__device__ float g_item  [BMAX][D];
__device__ float g_y     [BMAX][D];

// ------------------------------------------------------------------
__global__ void k_zero()
{
    for (int i = threadIdx.x; i < NHOP * NREL; i += blockDim.x) {
        ((int*)g_count)[i]  = 0;
        ((int*)g_cursor)[i] = 0;
    }
}

__global__ void k_count(const int* __restrict__ mem_r, int B)
{
    int idx = blockIdx.x * blockDim.x + threadIdx.x;
    int total = NHOP * B * NMEM;
    if (idx < total) {
        int hop = idx / (B * NMEM);
        atomicAdd(&g_count[hop][mem_r[idx]], 1);
    }
}

__global__ void k_scan()
{
    int h = threadIdx.x;
    if (h < NHOP) {
        int acc = 0;
        for (int r = 0; r < NREL; ++r) { g_off[h][r] = acc; acc += g_count[h][r]; }
        g_off[h][NREL] = acc;
    }
}

__global__ void k_scatter(const int* __restrict__ mem_r, int B)
{
    int idx = blockIdx.x * blockDim.x + threadIdx.x;
    int total = NHOP * B * NMEM;
    if (idx < total) {
        int hop  = idx / (B * NMEM);
        int slot = idx - hop * (B * NMEM);
        int r    = mem_r[idx];
        int pos  = atomicAdd(&g_cursor[hop][r], 1);
        g_slots[hop][g_off[hop][r] + pos] = slot;
    }
}

__global__ void k_init(const int* __restrict__ items,
                       const float* __restrict__ entity)
{
    int b = blockIdx.x, t = threadIdx.x;
    g_item[b][t] = entity[(size_t)items[b] * D + t];
    g_y[b][t]    = 0.0f;
}

// ------------------------------------------------------------------
// logits for one hop: per (relation, 64-slot tile) compute
//   Y[s][i] = (R @ h_s)_i        (GEMM, R staged once in smem)
//   logit_s = dot(Y[s], item_{b(s)})
// Block: 128 threads, thread (ts,ti) owns a 4x8 micro-tile of Y.
__global__ __launch_bounds__(128)
void k_logits(const int* __restrict__ mem_h,
              const float* __restrict__ entity,
              const float* __restrict__ rel,
              int hop, int B)
{
    const int r = blockIdx.x;
    const int n = g_count[hop][r];
    if ((int)(blockIdx.y * TILE) >= n) return;
    const int base = g_off[hop][r];

    const int tid  = threadIdx.x;
    const int lane = tid & 31;
    const int warp = tid >> 5;
    const int ts   = tid >> 3;   // 0..15  -> slot group of 4
    const int ti   = tid & 7;    // 0..7   -> i group of 8

    __shared__ float RsT[D][PAD];     // RsT[j][i] = R[i][j]
    __shared__ float Hs [TILE][PAD];  // phase1: HsT[j][s]; phase2: Y[s][i]
    __shared__ int   slot_s[TILE];

    // stage R transposed (read once per block, serves all tiles)
    for (int idx = tid; idx < D * D; idx += 128) {
        int i = idx >> 6, j = idx & 63;
        RsT[j][i] = rel[(size_t)r * (D * D) + idx];
    }

    for (int t0 = blockIdx.y * TILE; t0 < n; t0 += gridDim.y * TILE) {
        __syncthreads();  // protect prior-iter Y reads + RsT store (1st iter)

        // gather h rows, transposed into HsT[j][s]
        for (int s = warp; s < TILE; s += 4) {
            int valid = (t0 + s) < n;
            int slot  = valid ? g_slots[hop][base + t0 + s] : 0;
            if (lane == 0) slot_s[s] = valid ? slot : -1;
            const float* H = entity +
                (size_t)mem_h[(size_t)hop * B * NMEM + slot] * D;
            Hs[lane][s]      = valid ? H[lane]      : 0.0f;
            Hs[lane + 32][s] = valid ? H[lane + 32] : 0.0f;
        }
        __syncthreads();

        float acc[4][8];
        #pragma unroll
        for (int k = 0; k < 4; ++k)
            #pragma unroll
            for (int kk = 0; kk < 8; ++kk) acc[k][kk] = 0.0f;

        #pragma unroll 8
        for (int j = 0; j < D; ++j) {
            float4 a4 = *(const float4*)&Hs[j][ts * 4];
            float4 b0 = *(const float4*)&RsT[j][ti * 8];
            float4 b1 = *(const float4*)&RsT[j][ti * 8 + 4];
            float a[4] = {a4.x, a4.y, a4.z, a4.w};
            float bb[8] = {b0.x, b0.y, b0.z, b0.w, b1.x, b1.y, b1.z, b1.w};
            #pragma unroll
            for (int k = 0; k < 4; ++k)
                #pragma unroll
                for (int kk = 0; kk < 8; ++kk)
                    acc[k][kk] = fmaf(a[k], bb[kk], acc[k][kk]);
        }

        __syncthreads();
        // write Y[s][i] back into the Hs buffer
        #pragma unroll
        for (int k = 0; k < 4; ++k)
            #pragma unroll
            for (int kk = 0; kk < 8; ++kk)
                Hs[ts * 4 + k][ti * 8 + kk] = acc[k][kk];
        __syncthreads();

        // logit_s = dot(Y[s], item_b) ; 2 threads per slot
        {
            int s    = tid >> 1;
            int half = tid & 1;
            int slot = slot_s[s];
            float part = 0.0f;
            if (slot >= 0) {
                int b = slot >> 4;  // slot = b*NMEM + m, NMEM = 16
                const float4* yv = (const float4*)&Hs[s][half * 32];
                const float4* iv = (const float4*)&g_item[b][half * 32];
                #pragma unroll
                for (int q = 0; q < 8; ++q) {
                    float4 y4 = yv[q], i4 = iv[q];
                    part = fmaf(y4.x, i4.x, part);
                    part = fmaf(y4.y, i4.y, part);
                    part = fmaf(y4.z, i4.z, part);
                    part = fmaf(y4.w, i4.w, part);
                }
            }
            part += __shfl_xor_sync(0xffffffffu, part, 1);
            if (half == 0 && slot >= 0) g_logits[hop][slot] = part;
        }
    }
}

// ------------------------------------------------------------------
// per-batch-element: softmax over 16 slots, o = probs.t, y += o,
// item = W @ (item + o); final hop also writes score = dot(item, y)
__global__ __launch_bounds__(64)
void k_update(const int* __restrict__ mem_t,
              const float* __restrict__ entity,
              const float* __restrict__ W,
              float* __restrict__ out,
              int hop, int B)
{
    const int b = blockIdx.x, tid = threadIdx.x;
    __shared__ float probs[NMEM];
    __shared__ float v_s[D];
    __shared__ float red[2];

    const float* lg = &g_logits[hop][b * NMEM];
    if (tid < NMEM) {
        float mx = lg[0];
        #pragma unroll
        for (int k = 1; k < NMEM; ++k) mx = fmaxf(mx, lg[k]);
        probs[tid] = expf(lg[tid] - mx);
    }
    float item_old = g_item[b][tid];
    __syncthreads();

    float denom = 0.0f;
    #pragma unroll
    for (int m = 0; m < NMEM; ++m) denom += probs[m];

    const int* tids = mem_t + (size_t)hop * B * NMEM + b * NMEM;
    float o = 0.0f;
    #pragma unroll
    for (int m = 0; m < NMEM; ++m)
        o = fmaf(probs[m], entity[(size_t)tids[m] * D + tid], o);
    o /= denom;

    float ynew = g_y[b][tid] + o;
    g_y[b][tid] = ynew;
    v_s[tid] = item_old + o;
    __syncthreads();

    float acc = 0.0f;
    const float* wr = W + tid * D;
    #pragma unroll
    for (int j = 0; j < D; ++j) acc = fmaf(wr[j], v_s[j], acc);
    g_item[b][tid] = acc;

    if (hop == NHOP - 1) {
        float p = acc * ynew;
        #pragma unroll
        for (int off = 16; off > 0; off >>= 1)
            p += __shfl_xor_sync(0xffffffffu, p, off);
        if ((tid & 31) == 0) red[tid >> 5] = p;
        __syncthreads();
        if (tid == 0) out[b] = red[0] + red[1];
    }
}

// ------------------------------------------------------------------
extern "C" void kernel_launch(void* const* d_in, const int* in_sizes, int n_in,
                              void* d_out, int out_size)
{
    const int*   items  = (const int*)  d_in[0];
    const int*   mem_h  = (const int*)  d_in[1];
    const int*   mem_r  = (const int*)  d_in[2];
    const int*   mem_t  = (const int*)  d_in[3];
    const float* entity = (const float*)d_in[4];
    const float* rel    = (const float*)d_in[5];
    const float* W      = (const float*)d_in[6];
    float*       out    = (float*)d_out;

    const int B = in_sizes[0];            // 4096
    const int total = NHOP * B * NMEM;

    k_zero   <<<1, 256>>>();
    k_count  <<<(total + 255) / 256, 256>>>(mem_r, B);
    k_scan   <<<1, 32>>>();
    k_scatter<<<(total + 255) / 256, 256>>>(mem_r, B);
    k_init   <<<B, 64>>>(items, entity);

    for (int hop = 0; hop < NHOP; ++hop) {
        dim3 grid(NREL, 8);
        k_logits<<<grid, 128>>>(mem_h, entity, rel, hop, B);
        k_update<<<B, 64>>>(mem_t, entity, W, out, hop, B);
    }
}

// round 5
// speedup vs baseline: 1.4996x; 1.2619x over previous
#include <cuda_runtime.h>

#define D     64
#define NMEM  16
#define NHOP  2
#define NREL  200
#define BMAX  4096
#define SMAX  (BMAX * NMEM)   // 65536 slots per hop
#define TILE  64
#define PAD   68              // 272B rows: float4-aligned, 4-way-max STS conflicts
#define CBLK  32              // histogram/scatter blocks per hop
#define YB    6               // tile-blocks per relation in k_gemm

// ---- persistent scratch (no runtime allocation allowed) ----
__device__ int   g_parthist[NHOP][CBLK][NREL];
__device__ int   g_off   [NHOP][NREL + 1];
__device__ int   g_cursor[NHOP][NREL];
__device__ int   g_slots [NHOP][SMAX];
__device__ float g_Y     [NHOP][SMAX][D];   // Y[slot] = R_{r(slot)} @ h_slot
__device__ float g_item  [BMAX][D];
__device__ float g_y     [BMAX][D];

// ------------------------------------------------------------------
// Per-block smem histogram -> partial counts (no global atomics, no zero pass)
__global__ __launch_bounds__(256)
void k_count(const int* __restrict__ mem_r, int B)
{
    __shared__ int hist[NREL];
    const int hop   = blockIdx.y;
    const int total = B * NMEM;
    const int chunk = (total + CBLK - 1) / CBLK;
    const int start = blockIdx.x * chunk;

    for (int i = threadIdx.x; i < NREL; i += 256) hist[i] = 0;
    __syncthreads();

    for (int k = threadIdx.x; k < chunk; k += 256) {
        int idx = start + k;
        if (idx < total) atomicAdd(&hist[mem_r[hop * total + idx]], 1);
    }
    __syncthreads();

    for (int i = threadIdx.x; i < NREL; i += 256)
        g_parthist[hop][blockIdx.x][i] = hist[i];
}

// Sum partials, exclusive scan per hop, zero cursors. One block.
__global__ __launch_bounds__(512)
void k_scan()
{
    __shared__ int cnt[NHOP][NREL];
    const int tid = threadIdx.x;
    if (tid < NHOP * NREL) {
        int hop = tid / NREL, r = tid - hop * NREL;
        int s = 0;
        #pragma unroll 8
        for (int b = 0; b < CBLK; ++b) s += g_parthist[hop][b][r];
        cnt[hop][r] = s;
        g_cursor[hop][r] = 0;
    }
    __syncthreads();
    if (tid < NHOP) {
        int acc = 0;
        for (int r = 0; r < NREL; ++r) { g_off[tid][r] = acc; acc += cnt[tid][r]; }
        g_off[tid][NREL] = acc;
    }
}

// Scatter with smem-privatized local ranks: ~200 global atomics per block.
__global__ __launch_bounds__(256)
void k_scatter(const int* __restrict__ mem_r, int B)
{
    __shared__ int hist[NREL];
    __shared__ int base_s[NREL];
    const int hop   = blockIdx.y;
    const int total = B * NMEM;
    const int chunk = (total + CBLK - 1) / CBLK;   // 2048 for B=4096
    const int start = blockIdx.x * chunk;

    for (int i = threadIdx.x; i < NREL; i += 256) hist[i] = 0;
    __syncthreads();

    int rr[8], lrank[8];
    #pragma unroll
    for (int t = 0; t < 8; ++t) {
        int k = t * 256 + threadIdx.x;
        rr[t] = -1;
        if (k < chunk && start + k < total) {
            rr[t]    = mem_r[hop * total + start + k];
            lrank[t] = atomicAdd(&hist[rr[t]], 1);
        }
    }
    __syncthreads();

    for (int i = threadIdx.x; i < NREL; i += 256) {
        int c = hist[i];
        base_s[i] = g_off[hop][i] + (c ? atomicAdd(&g_cursor[hop][i], c) : 0);
    }
    __syncthreads();

    #pragma unroll
    for (int t = 0; t < 8; ++t)
        if (rr[t] >= 0)
            g_slots[hop][base_s[rr[t]] + lrank[t]] = start + t * 256 + threadIdx.x;
}

// ------------------------------------------------------------------
// Y[slot] = R @ h_slot for ALL slots of BOTH hops.
// Block: (relation, tile-block, hop), 128 threads, 4x8 register micro-tile.
__global__ __launch_bounds__(128)
void k_gemm(const int* __restrict__ mem_h,
            const float* __restrict__ entity,
            const float* __restrict__ rel,
            int B)
{
    const int hop  = blockIdx.z;
    const int r    = blockIdx.x;
    const int base = g_off[hop][r];
    const int n    = g_off[hop][r + 1] - base;
    if ((int)(blockIdx.y * TILE) >= n) return;

    __shared__ float RsT[D][PAD];     // RsT[j][i] = R[i][j]
    __shared__ float Hs [D][PAD];     // Hs[j][s]  = h_s[j]
    __shared__ int   slot_s[TILE];

    const int tid  = threadIdx.x;
    const int lane = tid & 31;
    const int warp = tid >> 5;
    const int ts   = tid >> 3;   // 0..15 -> slot group of 4
    const int ti   = tid & 7;    // 0..7  -> dim group of 8

    const float* __restrict__ Rp = rel + (size_t)r * (D * D);
    for (int idx = tid; idx < D * D; idx += 128) {
        int i = idx >> 6, j = idx & 63;
        RsT[j][i] = Rp[idx];
    }
    const int* __restrict__ mh = mem_h + (size_t)hop * B * NMEM;

    for (int t0 = blockIdx.y * TILE; t0 < n; t0 += YB * TILE) {
        __syncthreads();   // protects RsT (1st iter) + prior-iter Hs/slot_s reads

        for (int s = warp; s < TILE; s += 4) {
            bool valid = (t0 + s) < n;
            int  slot  = valid ? g_slots[hop][base + t0 + s] : 0;
            if (lane == 0) slot_s[s] = valid ? slot : -1;
            const float* H = entity + (size_t)mh[slot] * D;
            Hs[lane][s]      = valid ? H[lane]      : 0.0f;
            Hs[lane + 32][s] = valid ? H[lane + 32] : 0.0f;
        }
        __syncthreads();

        float acc[4][8];
        #pragma unroll
        for (int k = 0; k < 4; ++k)
            #pragma unroll
            for (int kk = 0; kk < 8; ++kk) acc[k][kk] = 0.0f;

        #pragma unroll 8
        for (int j = 0; j < D; ++j) {
            float4 a4 = *(const float4*)&Hs[j][ts * 4];
            float4 b0 = *(const float4*)&RsT[j][ti * 8];
            float4 b1 = *(const float4*)&RsT[j][ti * 8 + 4];
            float a[4]  = {a4.x, a4.y, a4.z, a4.w};
            float bb[8] = {b0.x, b0.y, b0.z, b0.w, b1.x, b1.y, b1.z, b1.w};
            #pragma unroll
            for (int k = 0; k < 4; ++k)
                #pragma unroll
                for (int kk = 0; kk < 8; ++kk)
                    acc[k][kk] = fmaf(a[k], bb[kk], acc[k][kk]);
        }

        // write Y straight from registers (two float4s per slot per thread)
        #pragma unroll
        for (int k = 0; k < 4; ++k) {
            int slot = slot_s[ts * 4 + k];
            if (slot >= 0) {
                float4* dst = (float4*)&g_Y[hop][slot][ti * 8];
                dst[0] = make_float4(acc[k][0], acc[k][1], acc[k][2], acc[k][3]);
                dst[1] = make_float4(acc[k][4], acc[k][5], acc[k][6], acc[k][7]);
            }
        }
    }
}

// ------------------------------------------------------------------
// Per batch element: logits = Y . item, softmax, o = probs . t,
// y += o, item = W @ (item + o); last hop writes score.
__global__ __launch_bounds__(128)
void k_upd(const int* __restrict__ items,
           const int* __restrict__ mem_t,
           const float* __restrict__ entity,
           const float* __restrict__ W,
           float* __restrict__ out,
           int hop, int B)
{
    const int b = blockIdx.x, tid = threadIdx.x;
    const int lane = tid & 31, warp = tid >> 5;

    __shared__ float item_sv[D];
    __shared__ float vbuf[D];
    __shared__ float lgs[NMEM];
    __shared__ float probs[NMEM];
    __shared__ float red[2];

    if (tid < D)
        item_sv[tid] = hop ? g_item[b][tid]
                           : entity[(size_t)items[b] * D + tid];
    __syncthreads();

    // logits: warp w handles slots 4w..4w+3, Y rows are contiguous 256B
    #pragma unroll
    for (int s = 0; s < 4; ++s) {
        int m = warp * 4 + s;
        const float* Yp = g_Y[hop][b * NMEM + m];
        float v = Yp[lane] * item_sv[lane] + Yp[lane + 32] * item_sv[lane + 32];
        #pragma unroll
        for (int off = 16; off > 0; off >>= 1)
            v += __shfl_xor_sync(0xffffffffu, v, off);
        if (lane == 0) lgs[m] = v;
    }
    __syncthreads();

    if (tid < NMEM) {
        float mx = lgs[0];
        #pragma unroll
        for (int k = 1; k < NMEM; ++k) mx = fmaxf(mx, lgs[k]);
        probs[tid] = expf(lgs[tid] - mx);
    }
    float item_old = (tid < D) ? item_sv[tid] : 0.0f;
    __syncthreads();

    if (tid < D) {
        float denom = 0.0f;
        #pragma unroll
        for (int m = 0; m < NMEM; ++m) denom += probs[m];

        const int* tp = mem_t + (size_t)hop * B * NMEM + b * NMEM;
        float o = 0.0f;
        #pragma unroll
        for (int m = 0; m < NMEM; ++m)
            o = fmaf(probs[m], entity[(size_t)tp[m] * D + tid], o);
        o /= denom;

        float ynew = (hop ? g_y[b][tid] : 0.0f) + o;
        g_y[b][tid] = ynew;
        vbuf[tid]   = item_old + o;
        item_sv[tid] = ynew;          // stash for score (logit reads are done)
    }
    __syncthreads();

    if (tid < D) {
        float acc = 0.0f;
        const float* wr = W + tid * D;
        #pragma unroll
        for (int j = 0; j < D; ++j) acc = fmaf(wr[j], vbuf[j], acc);
        g_item[b][tid] = acc;

        if (hop == NHOP - 1) {
            float p = acc * item_sv[tid];   // item_final * y
            #pragma unroll
            for (int off = 16; off > 0; off >>= 1)
                p += __shfl_xor_sync(0xffffffffu, p, off);
            if (lane == 0) red[warp] = p;
        }
    }
    if (hop == NHOP - 1) {
        __syncthreads();
        if (tid == 0) out[b] = red[0] + red[1];
    }
}

// ------------------------------------------------------------------
extern "C" void kernel_launch(void* const* d_in, const int* in_sizes, int n_in,
                              void* d_out, int out_size)
{
    const int*   items  = (const int*)  d_in[0];
    const int*   mem_h  = (const int*)  d_in[1];
    const int*   mem_r  = (const int*)  d_in[2];
    const int*   mem_t  = (const int*)  d_in[3];
    const float* entity = (const float*)d_in[4];
    const float* rel    = (const float*)d_in[5];
    const float* W      = (const float*)d_in[6];
    float*       out    = (float*)d_out;

    const int B = in_sizes[0];   // 4096

    k_count  <<<dim3(CBLK, NHOP), 256>>>(mem_r, B);
    k_scan   <<<1, 512>>>();
    k_scatter<<<dim3(CBLK, NHOP), 256>>>(mem_r, B);
    k_gemm   <<<dim3(NREL, YB, NHOP), 128>>>(mem_h, entity, rel, B);
    k_upd    <<<B, 128>>>(items, mem_t, entity, W, out, 0, B);
    k_upd    <<<B, 128>>>(items, mem_t, entity, W, out, 1, B);
}

// round 6
// speedup vs baseline: 3.7572x; 2.5056x over previous
#include <cuda_runtime.h>

#define D     64
#define NMEM  16
#define NHOP  2
#define NREL  200
#define BMAX  4096
#define SMAX  (BMAX * NMEM)   // 65536 slots per hop
#define TM    128             // slots per GEMM tile
#define RPAD  68              // RsT row stride (floats)
#define HPAD  132             // Hs  row stride (floats)
#define CBLK  32              // histogram/scatter blocks per hop
#define YB    3               // tile-blocks per relation

#define GEMM_SMEM ((D * RPAD + D * HPAD + TM) * 4)

// ---- persistent scratch (no runtime allocation allowed) ----
__device__ int   g_parthist[NHOP][CBLK][NREL];
__device__ int   g_off   [NHOP][NREL + 1];
__device__ int   g_cursor[NHOP][NREL];
__device__ int   g_slots [NHOP][SMAX];
__device__ float g_Y     [NHOP][SMAX][D];   // Y[slot] = R_{r(slot)} @ h_slot
__device__ float g_item  [BMAX][D];
__device__ float g_y     [BMAX][D];
__device__ float g_Wt    [D * D];           // Wt[j][i] = W[i][j]

// ------------------------------------------------------------------
__global__ __launch_bounds__(256)
void k_count(const int* __restrict__ mem_r, int B)
{
    __shared__ int hist[NREL];
    const int hop   = blockIdx.y;
    const int total = B * NMEM;
    const int chunk = (total + CBLK - 1) / CBLK;
    const int start = blockIdx.x * chunk;

    for (int i = threadIdx.x; i < NREL; i += 256) hist[i] = 0;
    __syncthreads();

    const int* src = mem_r + hop * total;
    if ((chunk & 7) == 0 && start + chunk <= total) {
        int base = start + threadIdx.x * 8;
        if (base + 8 <= start + chunk) {
            int4 v0 = *(const int4*)(src + base);
            int4 v1 = *(const int4*)(src + base + 4);
            atomicAdd(&hist[v0.x], 1); atomicAdd(&hist[v0.y], 1);
            atomicAdd(&hist[v0.z], 1); atomicAdd(&hist[v0.w], 1);
            atomicAdd(&hist[v1.x], 1); atomicAdd(&hist[v1.y], 1);
            atomicAdd(&hist[v1.z], 1); atomicAdd(&hist[v1.w], 1);
        }
    } else {
        for (int k = threadIdx.x; k < chunk; k += 256) {
            int idx = start + k;
            if (idx < total) atomicAdd(&hist[src[idx]], 1);
        }
    }
    __syncthreads();

    for (int i = threadIdx.x; i < NREL; i += 256)
        g_parthist[hop][blockIdx.x][i] = hist[i];
}

// Sum partials, scan, zero cursors; also transpose W (independent work).
__global__ __launch_bounds__(512)
void k_scan(const float* __restrict__ W)
{
    __shared__ int cnt[NHOP][NREL];
    const int tid = threadIdx.x;
    if (tid < NHOP * NREL) {
        int hop = tid / NREL, r = tid - hop * NREL;
        int s = 0;
        #pragma unroll 8
        for (int b = 0; b < CBLK; ++b) s += g_parthist[hop][b][r];
        cnt[hop][r] = s;
        g_cursor[hop][r] = 0;
    }
    for (int idx = tid; idx < D * D; idx += 512)
        g_Wt[(idx & (D - 1)) * D + (idx >> 6)] = W[idx];
    __syncthreads();
    if (tid < NHOP) {
        int acc = 0;
        for (int r = 0; r < NREL; ++r) { g_off[tid][r] = acc; acc += cnt[tid][r]; }
        g_off[tid][NREL] = acc;
    }
}

__global__ __launch_bounds__(256)
void k_scatter(const int* __restrict__ mem_r, int B)
{
    __shared__ int hist[NREL];
    __shared__ int base_s[NREL];
    const int hop   = blockIdx.y;
    const int total = B * NMEM;
    const int chunk = (total + CBLK - 1) / CBLK;
    const int start = blockIdx.x * chunk;

    for (int i = threadIdx.x; i < NREL; i += 256) hist[i] = 0;
    __syncthreads();

    const int* src = mem_r + hop * total;
    int rr[8], lrank[8], idx0 = start + threadIdx.x * 8;
    bool vec = ((chunk & 7) == 0) && (idx0 + 8 <= start + chunk) &&
               (start + chunk <= total);
    if (vec) {
        int4 v0 = *(const int4*)(src + idx0);
        int4 v1 = *(const int4*)(src + idx0 + 4);
        rr[0]=v0.x; rr[1]=v0.y; rr[2]=v0.z; rr[3]=v0.w;
        rr[4]=v1.x; rr[5]=v1.y; rr[6]=v1.z; rr[7]=v1.w;
        #pragma unroll
        for (int t = 0; t < 8; ++t) lrank[t] = atomicAdd(&hist[rr[t]], 1);
    } else {
        #pragma unroll
        for (int t = 0; t < 8; ++t) {
            int k = threadIdx.x * 8 + t;
            rr[t] = -1;
            if (k < chunk && start + k < total) {
                rr[t]    = src[start + k];
                lrank[t] = atomicAdd(&hist[rr[t]], 1);
            }
        }
    }
    __syncthreads();

    for (int i = threadIdx.x; i < NREL; i += 256) {
        int c = hist[i];
        base_s[i] = g_off[hop][i] + (c ? atomicAdd(&g_cursor[hop][i], c) : 0);
    }
    __syncthreads();

    #pragma unroll
    for (int t = 0; t < 8; ++t)
        if (vec || rr[t] >= 0)
            g_slots[hop][base_s[rr[t]] + lrank[t]] = idx0 + t;
}

// ------------------------------------------------------------------
// Y[slot] = R @ h_slot for ALL slots of BOTH hops.
// 128 threads, 128-slot x 64-dim tile, 8x8 register micro-tile per thread.
__global__ __launch_bounds__(128, 4)
void k_gemm(const int* __restrict__ mem_h,
            const float* __restrict__ entity,
            const float* __restrict__ rel,
            int B)
{
    const int hop  = blockIdx.z;
    const int r    = blockIdx.x;
    const int base = g_off[hop][r];
    const int n    = g_off[hop][r + 1] - base;
    if ((int)(blockIdx.y * TM) >= n) return;

    extern __shared__ float smem[];
    float (*RsT)[RPAD] = (float(*)[RPAD])smem;              // RsT[j][i] = R[i][j]
    float (*Hs)[HPAD]  = (float(*)[HPAD])(smem + D * RPAD); // Hs[j][s]  = h_s[j]
    int*  slot_s       = (int*)(smem + D * RPAD + D * HPAD);

    const int tid  = threadIdx.x;
    const int lane = tid & 31;
    const int warp = tid >> 5;
    const int ts   = tid >> 3;   // 0..15 -> slot group of 8
    const int ti   = tid & 7;    // 0..7  -> dim group of 8

    const float* __restrict__ Rp = rel + (size_t)r * (D * D);
    for (int idx = tid; idx < D * D; idx += 128) {
        int i = idx >> 6, j = idx & 63;
        RsT[j][i] = Rp[idx];
    }
    const int* __restrict__ mh = mem_h + (size_t)hop * B * NMEM;

    for (int t0 = blockIdx.y * TM; t0 < n; t0 += YB * TM) {
        __syncthreads();   // protects RsT (1st iter) + prior-iter Hs/slot_s

        #pragma unroll 4
        for (int s = warp; s < TM; s += 4) {
            bool valid = (t0 + s) < n;
            int  slot  = valid ? g_slots[hop][base + t0 + s] : 0;
            if (lane == 0) slot_s[s] = valid ? slot : -1;
            const float* H = entity + (size_t)mh[slot] * D;
            Hs[lane][s]      = valid ? H[lane]      : 0.0f;
            Hs[lane + 32][s] = valid ? H[lane + 32] : 0.0f;
        }
        __syncthreads();

        float acc[8][8];
        #pragma unroll
        for (int k = 0; k < 8; ++k)
            #pragma unroll
            for (int kk = 0; kk < 8; ++kk) acc[k][kk] = 0.0f;

        #pragma unroll 4
        for (int j = 0; j < D; ++j) {
            float4 a0 = *(const float4*)&Hs[j][ts * 8];
            float4 a1 = *(const float4*)&Hs[j][ts * 8 + 4];
            float4 b0 = *(const float4*)&RsT[j][ti * 8];
            float4 b1 = *(const float4*)&RsT[j][ti * 8 + 4];
            float a[8]  = {a0.x, a0.y, a0.z, a0.w, a1.x, a1.y, a1.z, a1.w};
            float bb[8] = {b0.x, b0.y, b0.z, b0.w, b1.x, b1.y, b1.z, b1.w};
            #pragma unroll
            for (int k = 0; k < 8; ++k)
                #pragma unroll
                for (int kk = 0; kk < 8; ++kk)
                    acc[k][kk] = fmaf(a[k], bb[kk], acc[k][kk]);
        }

        #pragma unroll
        for (int k = 0; k < 8; ++k) {
            int slot = slot_s[ts * 8 + k];
            if (slot >= 0) {
                float4* dst = (float4*)&g_Y[hop][slot][ti * 8];
                dst[0] = make_float4(acc[k][0], acc[k][1], acc[k][2], acc[k][3]);
                dst[1] = make_float4(acc[k][4], acc[k][5], acc[k][6], acc[k][7]);
            }
        }
    }
}

// ------------------------------------------------------------------
// 2 batch elements per 128-thread block. sub = tid>>6 selects b.
__global__ __launch_bounds__(128)
void k_upd(const int* __restrict__ items,
           const int* __restrict__ mem_t,
           const float* __restrict__ entity,
           float* __restrict__ out,
           int hop, int B)
{
    const int tid  = threadIdx.x;
    const int sub  = tid >> 6;          // 0 / 1
    const int t    = tid & 63;
    const int lane = tid & 31;
    const int warp = tid >> 5;          // 0,1 -> sub0 ; 2,3 -> sub1
    const int wH   = warp & 1;          // warp within half
    const int b    = blockIdx.x * 2 + sub;

    __shared__ float item_sv[2][D];
    __shared__ float vbuf[2][D];
    __shared__ float lgs[2][NMEM];
    __shared__ float probs[2][NMEM];
    __shared__ float red[4];

    float item = hop ? g_item[b][t] : entity[(size_t)items[b] * D + t];
    item_sv[sub][t] = item;
    __syncthreads();

    // logits: each warp handles 8 of its b's 16 slots
    #pragma unroll
    for (int s = 0; s < 8; ++s) {
        int m = wH * 8 + s;
        const float* Yp = g_Y[hop][b * NMEM + m];
        float v = Yp[lane] * item_sv[sub][lane] +
                  Yp[lane + 32] * item_sv[sub][lane + 32];
        #pragma unroll
        for (int off = 16; off > 0; off >>= 1)
            v += __shfl_xor_sync(0xffffffffu, v, off);
        if (lane == 0) lgs[sub][m] = v;
    }
    __syncthreads();

    if (t < NMEM) {
        float mx = lgs[sub][0];
        #pragma unroll
        for (int k = 1; k < NMEM; ++k) mx = fmaxf(mx, lgs[sub][k]);
        probs[sub][t] = expf(lgs[sub][t] - mx);
    }
    __syncthreads();

    float denom = 0.0f;
    #pragma unroll
    for (int m = 0; m < NMEM; ++m) denom += probs[sub][m];

    const int* tp = mem_t + (size_t)hop * B * NMEM + b * NMEM;
    float o = 0.0f;
    #pragma unroll
    for (int m = 0; m < NMEM; ++m)
        o = fmaf(probs[sub][m], entity[(size_t)tp[m] * D + t], o);
    o /= denom;

    float ynew = (hop ? g_y[b][t] : 0.0f) + o;
    g_y[b][t]   = ynew;
    vbuf[sub][t] = item + o;
    __syncthreads();

    // item_new[t] = sum_j Wt[j][t] * v[j]   (coalesced Wt reads)
    float acc = 0.0f;
    #pragma unroll 8
    for (int j = 0; j < D; ++j)
        acc = fmaf(g_Wt[j * D + t], vbuf[sub][j], acc);
    g_item[b][t] = acc;

    if (hop == NHOP - 1) {
        float p = acc * ynew;
        #pragma unroll
        for (int off = 16; off > 0; off >>= 1)
            p += __shfl_xor_sync(0xffffffffu, p, off);
        if (lane == 0) red[warp] = p;
        __syncthreads();
        if (tid == 0)  out[b]     = red[0] + red[1];
        if (tid == 64) out[b]     = red[2] + red[3];
    }
}

// ------------------------------------------------------------------
extern "C" void kernel_launch(void* const* d_in, const int* in_sizes, int n_in,
                              void* d_out, int out_size)
{
    const int*   items  = (const int*)  d_in[0];
    const int*   mem_h  = (const int*)  d_in[1];
    const int*   mem_r  = (const int*)  d_in[2];
    const int*   mem_t  = (const int*)  d_in[3];
    const float* entity = (const float*)d_in[4];
    const float* rel    = (const float*)d_in[5];
    const float* W      = (const float*)d_in[6];
    float*       out    = (float*)d_out;

    const int B = in_sizes[0];   // 4096

    static bool attr_set = false;
    if (!attr_set) {
        cudaFuncSetAttribute(k_gemm, cudaFuncAttributeMaxDynamicSharedMemorySize,
                             GEMM_SMEM);
        attr_set = true;
    }

    k_count  <<<dim3(CBLK, NHOP), 256>>>(mem_r, B);
    k_scan   <<<1, 512>>>(W);
    k_scatter<<<dim3(CBLK, NHOP), 256>>>(mem_r, B);
    k_gemm   <<<dim3(NREL, YB, NHOP), 128, GEMM_SMEM>>>(mem_h, entity, rel, B);
    k_upd    <<<B / 2, 128>>>(items, mem_t, entity, out, 0, B);
    k_upd    <<<B / 2, 128>>>(items, mem_t, entity, out, 1, B);
}

// round 8
// speedup vs baseline: 3.9508x; 1.0515x over previous
#include <cuda_runtime.h>
#include <cstdint>

#define D     64
#define NMEM  16
#define NHOP  2
#define NREL  200
#define BMAX  4096
#define SMAX  (BMAX * NMEM)   // 65536 slots per hop
#define TM    112             // slots per GEMM tile (16 ts-groups x 7)
#define RPAD  68              // RsT row stride (floats)
#define CBLK  32              // histogram/scatter blocks per hop

// smem layout for k_gemm (bytes)
#define ROFF   0
#define RBYTES (D * RPAD * 4)                 // 17408
#define HOFF   RBYTES
#define HROWB  256                            // 64 floats per row (skew wraps in-row)
#define HBYTES (TM * HROWB)                   // 28672
#define SOFF   (HOFF + 2 * HBYTES)
#define GEMM_SMEM (SOFF + 2 * TM * 4)

// ---- persistent scratch (no runtime allocation allowed) ----
__device__ int   g_parthist[NHOP][CBLK][NREL];
__device__ int   g_off   [NHOP][NREL + 1];
__device__ int   g_cursor[NHOP][NREL];
__device__ int   g_slots [NHOP][SMAX];
__device__ float g_Y     [NHOP][SMAX][D];   // Y[slot] = R_{r(slot)} @ h_slot
__device__ float g_Wt    [D * D];           // Wt[j][i] = W[i][j]

// ------------------------------------------------------------------
__device__ __forceinline__ uint32_t smem_u32(const void* p) {
    return (uint32_t)__cvta_generic_to_shared(p);
}
__device__ __forceinline__ void cp16(uint32_t dst, const void* src) {
    asm volatile("cp.async.cg.shared.global [%0], [%1], 16;\n"
                 :: "r"(dst), "l"(src));
}
__device__ __forceinline__ void cp_commit() {
    asm volatile("cp.async.commit_group;\n" ::);
}
template <int N>
__device__ __forceinline__ void cp_wait() {
    asm volatile("cp.async.wait_group %0;\n" :: "n"(N));
}

// ------------------------------------------------------------------
__global__ __launch_bounds__(256)
void k_count(const int* __restrict__ mem_r, int B)
{
    __shared__ int hist[NREL];
    const int hop   = blockIdx.y;
    const int total = B * NMEM;
    const int chunk = (total + CBLK - 1) / CBLK;
    const int start = blockIdx.x * chunk;

    for (int i = threadIdx.x; i < NREL; i += 256) hist[i] = 0;
    __syncthreads();

    const int* src = mem_r + hop * total;
    if ((chunk & 7) == 0 && start + chunk <= total) {
        int base = start + threadIdx.x * 8;
        if (base + 8 <= start + chunk) {
            int4 v0 = *(const int4*)(src + base);
            int4 v1 = *(const int4*)(src + base + 4);
            atomicAdd(&hist[v0.x], 1); atomicAdd(&hist[v0.y], 1);
            atomicAdd(&hist[v0.z], 1); atomicAdd(&hist[v0.w], 1);
            atomicAdd(&hist[v1.x], 1); atomicAdd(&hist[v1.y], 1);
            atomicAdd(&hist[v1.z], 1); atomicAdd(&hist[v1.w], 1);
        }
    } else {
        for (int k = threadIdx.x; k < chunk; k += 256) {
            int idx = start + k;
            if (idx < total) atomicAdd(&hist[src[idx]], 1);
        }
    }
    __syncthreads();

    for (int i = threadIdx.x; i < NREL; i += 256)
        g_parthist[hop][blockIdx.x][i] = hist[i];
}

__global__ __launch_bounds__(512)
void k_scan(const float* __restrict__ W)
{
    __shared__ int cnt[NHOP][NREL];
    const int tid = threadIdx.x;
    if (tid < NHOP * NREL) {
        int hop = tid / NREL, r = tid - hop * NREL;
        int s = 0;
        #pragma unroll 8
        for (int b = 0; b < CBLK; ++b) s += g_parthist[hop][b][r];
        cnt[hop][r] = s;
        g_cursor[hop][r] = 0;
    }
    for (int idx = tid; idx < D * D; idx += 512)
        g_Wt[(idx & (D - 1)) * D + (idx >> 6)] = W[idx];
    __syncthreads();
    if (tid < NHOP) {
        int acc = 0;
        for (int r = 0; r < NREL; ++r) { g_off[tid][r] = acc; acc += cnt[tid][r]; }
        g_off[tid][NREL] = acc;
    }
}

__global__ __launch_bounds__(256)
void k_scatter(const int* __restrict__ mem_r, int B)
{
    __shared__ int hist[NREL];
    __shared__ int base_s[NREL];
    const int hop   = blockIdx.y;
    const int total = B * NMEM;
    const int chunk = (total + CBLK - 1) / CBLK;
    const int start = blockIdx.x * chunk;

    for (int i = threadIdx.x; i < NREL; i += 256) hist[i] = 0;
    __syncthreads();

    const int* src = mem_r + hop * total;
    int rr[8], lrank[8], idx0 = start + threadIdx.x * 8;
    bool vec = ((chunk & 7) == 0) && (idx0 + 8 <= start + chunk) &&
               (start + chunk <= total);
    if (vec) {
        int4 v0 = *(const int4*)(src + idx0);
        int4 v1 = *(const int4*)(src + idx0 + 4);
        rr[0]=v0.x; rr[1]=v0.y; rr[2]=v0.z; rr[3]=v0.w;
        rr[4]=v1.x; rr[5]=v1.y; rr[6]=v1.z; rr[7]=v1.w;
        #pragma unroll
        for (int t = 0; t < 8; ++t) lrank[t] = atomicAdd(&hist[rr[t]], 1);
    } else {
        #pragma unroll
        for (int t = 0; t < 8; ++t) {
            int k = threadIdx.x * 8 + t;
            rr[t] = -1;
            if (k < chunk && start + k < total) {
                rr[t]    = src[start + k];
                lrank[t] = atomicAdd(&hist[rr[t]], 1);
            }
        }
    }
    __syncthreads();

    for (int i = threadIdx.x; i < NREL; i += 256) {
        int c = hist[i];
        base_s[i] = g_off[hop][i] + (c ? atomicAdd(&g_cursor[hop][i], c) : 0);
    }
    __syncthreads();

    #pragma unroll
    for (int t = 0; t < 8; ++t)
        if (vec || rr[t] >= 0)
            g_slots[hop][base_s[rr[t]] + lrank[t]] = idx0 + t;
}

// ------------------------------------------------------------------
// Y[slot] = R @ h_slot. One block per (relation, hop), cp.async
// double-buffered H gather, 7x8 register micro-tile, 128 threads.
// H rows are skewed IN-ROW: source chunk c of row lands at byte
// ((row&7)*16 + c*16) & 255 within the 256B row.
__global__ __launch_bounds__(128, 3)
void k_gemm(const int* __restrict__ mem_h,
            const float* __restrict__ entity,
            const float* __restrict__ rel,
            int B)
{
    const int hop  = blockIdx.y;
    const int r    = blockIdx.x;
    const int base = g_off[hop][r];
    const int n    = g_off[hop][r + 1] - base;
    if (n <= 0) return;
    const int ntiles = (n + TM - 1) / TM;

    extern __shared__ char smem[];
    float (*RsT)[RPAD] = (float(*)[RPAD])(smem + ROFF);
    const uint32_t hb[2] = { smem_u32(smem + HOFF),
                             smem_u32(smem + HOFF + HBYTES) };
    int* sslot = (int*)(smem + SOFF);

    const int tid  = threadIdx.x;
    const int ts   = tid >> 3;      // 0..15
    const int ti   = tid & 7;       // 0..7

    const int* __restrict__ mh = mem_h + (size_t)hop * B * NMEM;

    // prefetch helper: gather tile t into buffer bi (skew wraps inside row)
    auto prefetch = [&](int t, int bi) {
        int s = t * TM + tid;
        int slot = -1;
        if (tid < TM) {
            if (s < n) slot = g_slots[hop][base + s];
            sslot[bi * TM + tid] = slot;
            if (slot >= 0) {
                const char* src = (const char*)(entity + (size_t)mh[slot] * D);
                uint32_t rowbase = hb[bi] + tid * HROWB;
                const uint32_t sk = (tid & 7) * 16;
                #pragma unroll
                for (int c = 0; c < 16; ++c)
                    cp16(rowbase + ((sk + c * 16) & 255), src + c * 16);
            }
        }
        cp_commit();
    };

    prefetch(0, 0);

    // stage R transposed (one-time; overlaps with tile-0 gather)
    {
        const float* __restrict__ Rp = rel + (size_t)r * (D * D);
        for (int idx = tid; idx < D * D; idx += 128) {
            int i = idx >> 6, j = idx & 63;
            RsT[j][i] = Rp[idx];
        }
    }

    const float4* R4 = (const float4*)(smem + ROFF);

    for (int t = 0; t < ntiles; ++t) {
        const int bi = t & 1;
        if (t + 1 < ntiles) { prefetch(t + 1, bi ^ 1); cp_wait<1>(); }
        else                { cp_wait<0>(); }
        __syncthreads();   // gather(t) + R (1st iter) visible to all

        const float4* H4 = (const float4*)(smem + HOFF + bi * HBYTES);

        float acc[7][8];
        #pragma unroll
        for (int k = 0; k < 7; ++k)
            #pragma unroll
            for (int kk = 0; kk < 8; ++kk) acc[k][kk] = 0.0f;

        #pragma unroll 2
        for (int jq = 0; jq < 16; ++jq) {
            float af[7][4];
            #pragma unroll
            for (int k = 0; k < 7; ++k) {
                // row = ts + 16k (row&7 == ts&7); chunk jq sits at
                // float4 index ((ts&7) + jq) & 15 within the row
                float4 a = H4[(ts + 16 * k) * 16 + (((ts & 7) + jq) & 15)];
                af[k][0] = a.x; af[k][1] = a.y; af[k][2] = a.z; af[k][3] = a.w;
            }
            #pragma unroll
            for (int jj = 0; jj < 4; ++jj) {
                float4 b0 = R4[(4 * jq + jj) * (RPAD / 4) + ti * 2];
                float4 b1 = R4[(4 * jq + jj) * (RPAD / 4) + ti * 2 + 1];
                float bb[8] = {b0.x, b0.y, b0.z, b0.w, b1.x, b1.y, b1.z, b1.w};
                #pragma unroll
                for (int k = 0; k < 7; ++k) {
                    float av = af[k][jj];
                    #pragma unroll
                    for (int kk = 0; kk < 8; ++kk)
                        acc[k][kk] = fmaf(av, bb[kk], acc[k][kk]);
                }
            }
        }

        #pragma unroll
        for (int k = 0; k < 7; ++k) {
            int slot = sslot[bi * TM + ts + 16 * k];
            if (slot >= 0) {
                float4* dst = (float4*)&g_Y[hop][slot][ti * 8];
                dst[0] = make_float4(acc[k][0], acc[k][1], acc[k][2], acc[k][3]);
                dst[1] = make_float4(acc[k][4], acc[k][5], acc[k][6], acc[k][7]);
            }
        }
        __syncthreads();   // done reading buf bi before it is overwritten
    }
}

// ------------------------------------------------------------------
// Fused epilogue: both hops + score. 2 batch elements per block.
__global__ __launch_bounds__(128)
void k_upd(const int* __restrict__ items,
           const int* __restrict__ mem_t,
           const float* __restrict__ entity,
           float* __restrict__ out,
           int B)
{
    const int tid  = threadIdx.x;
    const int sub  = tid >> 6;
    const int t    = tid & 63;
    const int lane = tid & 31;
    const int warp = tid >> 5;
    const int wH   = warp & 1;
    const int b    = blockIdx.x * 2 + sub;

    __shared__ float item_sv[2][D];
    __shared__ float vbuf[2][D];
    __shared__ float lgs[2][NMEM];
    __shared__ float probs[2][NMEM];
    __shared__ float red[4];

    float item = entity[(size_t)items[b] * D + t];
    float y = 0.0f;

    #pragma unroll
    for (int hop = 0; hop < NHOP; ++hop) {
        item_sv[sub][t] = item;
        __syncthreads();

        #pragma unroll
        for (int s = 0; s < 8; ++s) {
            int m = wH * 8 + s;
            const float* Yp = g_Y[hop][b * NMEM + m];
            float v = Yp[lane] * item_sv[sub][lane] +
                      Yp[lane + 32] * item_sv[sub][lane + 32];
            #pragma unroll
            for (int off = 16; off > 0; off >>= 1)
                v += __shfl_xor_sync(0xffffffffu, v, off);
            if (lane == 0) lgs[sub][m] = v;
        }
        __syncthreads();

        if (t < NMEM) {
            float mx = lgs[sub][0];
            #pragma unroll
            for (int k = 1; k < NMEM; ++k) mx = fmaxf(mx, lgs[sub][k]);
            probs[sub][t] = expf(lgs[sub][t] - mx);
        }
        __syncthreads();

        float denom = 0.0f;
        #pragma unroll
        for (int m = 0; m < NMEM; ++m) denom += probs[sub][m];

        const int* tp = mem_t + (size_t)hop * B * NMEM + b * NMEM;
        float o = 0.0f;
        #pragma unroll
        for (int m = 0; m < NMEM; ++m)
            o = fmaf(probs[sub][m], entity[(size_t)tp[m] * D + t], o);
        o /= denom;

        y += o;
        vbuf[sub][t] = item + o;
        __syncthreads();

        float acc = 0.0f;
        #pragma unroll 8
        for (int j = 0; j < D; ++j)
            acc = fmaf(g_Wt[j * D + t], vbuf[sub][j], acc);
        item = acc;
        __syncthreads();
    }

    float p = item * y;
    #pragma unroll
    for (int off = 16; off > 0; off >>= 1)
        p += __shfl_xor_sync(0xffffffffu, p, off);
    if (lane == 0) red[warp] = p;
    __syncthreads();
    if (tid == 0)  out[b] = red[0] + red[1];
    if (tid == 64) out[b] = red[2] + red[3];
}

// ------------------------------------------------------------------
extern "C" void kernel_launch(void* const* d_in, const int* in_sizes, int n_in,
                              void* d_out, int out_size)
{
    const int*   items  = (const int*)  d_in[0];
    const int*   mem_h  = (const int*)  d_in[1];
    const int*   mem_r  = (const int*)  d_in[2];
    const int*   mem_t  = (const int*)  d_in[3];
    const float* entity = (const float*)d_in[4];
    const float* rel    = (const float*)d_in[5];
    const float* W      = (const float*)d_in[6];
    float*       out    = (float*)d_out;

    const int B = in_sizes[0];   // 4096

    static bool attr_set = false;
    if (!attr_set) {
        cudaFuncSetAttribute(k_gemm, cudaFuncAttributeMaxDynamicSharedMemorySize,
                             GEMM_SMEM);
        attr_set = true;
    }

    k_count  <<<dim3(CBLK, NHOP), 256>>>(mem_r, B);
    k_scan   <<<1, 512>>>(W);
    k_scatter<<<dim3(CBLK, NHOP), 256>>>(mem_r, B);
    k_gemm   <<<dim3(NREL, NHOP), 128, GEMM_SMEM>>>(mem_h, entity, rel, B);
    k_upd    <<<B / 2, 128>>>(items, mem_t, entity, out, B);
}

// round 9
// speedup vs baseline: 4.0375x; 1.0219x over previous
#include <cuda_runtime.h>
#include <cstdint>

#define D     64
#define NMEM  16
#define NHOP  2
#define NREL  200
#define BMAX  4096
#define SMAX  (BMAX * NMEM)   // 65536 slots per hop
#define TM    112             // slots per GEMM tile (16 ts-groups x 7)
#define RPAD  68              // RsT row stride (floats)
#define CBLK  32              // histogram/scatter blocks per hop

// smem layout for k_gemm (bytes)
#define ROFF   0
#define RBYTES (D * RPAD * 4)                 // 17408
#define HOFF   RBYTES
#define HROWB  256                            // 64 floats per row (skew wraps in-row)
#define HBYTES (TM * HROWB)                   // 28672
#define SOFF   (HOFF + 2 * HBYTES)
#define GEMM_SMEM (SOFF + 2 * TM * 4)

// ---- persistent scratch (no runtime allocation allowed) ----
__device__ int   g_parthist[NHOP][CBLK][NREL];
__device__ int   g_off   [NHOP][NREL + 1];
__device__ int   g_cursor[NHOP][NREL];
__device__ int   g_slots [NHOP][SMAX];
__device__ float g_Y     [NHOP][SMAX][D];   // Y[slot] = R_{r(slot)} @ h_slot
__device__ float g_Wt    [D * D];           // Wt[j][i] = W[i][j]

// ------------------------------------------------------------------
__device__ __forceinline__ uint32_t smem_u32(const void* p) {
    return (uint32_t)__cvta_generic_to_shared(p);
}
__device__ __forceinline__ void cp16(uint32_t dst, const void* src) {
    asm volatile("cp.async.cg.shared.global [%0], [%1], 16;\n"
                 :: "r"(dst), "l"(src));
}
__device__ __forceinline__ void cp_commit() {
    asm volatile("cp.async.commit_group;\n" ::);
}
template <int N>
__device__ __forceinline__ void cp_wait() {
    asm volatile("cp.async.wait_group %0;\n" :: "n"(N));
}

// packed f32x2 helpers
__device__ __forceinline__ unsigned long long pack2(float v) {
    unsigned long long r;
    asm("mov.b64 %0, {%1, %1};" : "=l"(r) : "f"(v));
    return r;
}
__device__ __forceinline__ void fma2(unsigned long long& d,
                                     unsigned long long a,
                                     unsigned long long b) {
    asm("fma.rn.f32x2 %0, %1, %2, %0;" : "+l"(d) : "l"(a), "l"(b));
}

// ------------------------------------------------------------------
__global__ __launch_bounds__(256)
void k_count(const int* __restrict__ mem_r, int B)
{
    __shared__ int hist[NREL];
    const int hop   = blockIdx.y;
    const int total = B * NMEM;
    const int chunk = (total + CBLK - 1) / CBLK;
    const int start = blockIdx.x * chunk;

    for (int i = threadIdx.x; i < NREL; i += 256) hist[i] = 0;
    __syncthreads();

    const int* src = mem_r + hop * total;
    if ((chunk & 7) == 0 && start + chunk <= total) {
        int base = start + threadIdx.x * 8;
        if (base + 8 <= start + chunk) {
            int4 v0 = *(const int4*)(src + base);
            int4 v1 = *(const int4*)(src + base + 4);
            atomicAdd(&hist[v0.x], 1); atomicAdd(&hist[v0.y], 1);
            atomicAdd(&hist[v0.z], 1); atomicAdd(&hist[v0.w], 1);
            atomicAdd(&hist[v1.x], 1); atomicAdd(&hist[v1.y], 1);
            atomicAdd(&hist[v1.z], 1); atomicAdd(&hist[v1.w], 1);
        }
    } else {
        for (int k = threadIdx.x; k < chunk; k += 256) {
            int idx = start + k;
            if (idx < total) atomicAdd(&hist[src[idx]], 1);
        }
    }
    __syncthreads();

    for (int i = threadIdx.x; i < NREL; i += 256)
        g_parthist[hop][blockIdx.x][i] = hist[i];
}

__global__ __launch_bounds__(512)
void k_scan(const float* __restrict__ W)
{
    __shared__ int cnt[NHOP][NREL];
    const int tid = threadIdx.x;
    if (tid < NHOP * NREL) {
        int hop = tid / NREL, r = tid - hop * NREL;
        int s = 0;
        #pragma unroll 8
        for (int b = 0; b < CBLK; ++b) s += g_parthist[hop][b][r];
        cnt[hop][r] = s;
        g_cursor[hop][r] = 0;
    }
    for (int idx = tid; idx < D * D; idx += 512)
        g_Wt[(idx & (D - 1)) * D + (idx >> 6)] = W[idx];
    __syncthreads();
    if (tid < NHOP) {
        int acc = 0;
        for (int r = 0; r < NREL; ++r) { g_off[tid][r] = acc; acc += cnt[tid][r]; }
        g_off[tid][NREL] = acc;
    }
}

__global__ __launch_bounds__(256)
void k_scatter(const int* __restrict__ mem_r, int B)
{
    __shared__ int hist[NREL];
    __shared__ int base_s[NREL];
    const int hop   = blockIdx.y;
    const int total = B * NMEM;
    const int chunk = (total + CBLK - 1) / CBLK;
    const int start = blockIdx.x * chunk;

    for (int i = threadIdx.x; i < NREL; i += 256) hist[i] = 0;
    __syncthreads();

    const int* src = mem_r + hop * total;
    int rr[8], lrank[8], idx0 = start + threadIdx.x * 8;
    bool vec = ((chunk & 7) == 0) && (idx0 + 8 <= start + chunk) &&
               (start + chunk <= total);
    if (vec) {
        int4 v0 = *(const int4*)(src + idx0);
        int4 v1 = *(const int4*)(src + idx0 + 4);
        rr[0]=v0.x; rr[1]=v0.y; rr[2]=v0.z; rr[3]=v0.w;
        rr[4]=v1.x; rr[5]=v1.y; rr[6]=v1.z; rr[7]=v1.w;
        #pragma unroll
        for (int t = 0; t < 8; ++t) lrank[t] = atomicAdd(&hist[rr[t]], 1);
    } else {
        #pragma unroll
        for (int t = 0; t < 8; ++t) {
            int k = threadIdx.x * 8 + t;
            rr[t] = -1;
            if (k < chunk && start + k < total) {
                rr[t]    = src[start + k];
                lrank[t] = atomicAdd(&hist[rr[t]], 1);
            }
        }
    }
    __syncthreads();

    for (int i = threadIdx.x; i < NREL; i += 256) {
        int c = hist[i];
        base_s[i] = g_off[hop][i] + (c ? atomicAdd(&g_cursor[hop][i], c) : 0);
    }
    __syncthreads();

    #pragma unroll
    for (int t = 0; t < 8; ++t)
        if (vec || rr[t] >= 0)
            g_slots[hop][base_s[rr[t]] + lrank[t]] = idx0 + t;
}

// ------------------------------------------------------------------
// Y[slot] = R @ h_slot. One block per (relation, hop), cp.async
// double-buffered H gather, 7x8 micro-tile with PACKED f32x2 FMAs.
__global__ __launch_bounds__(128, 3)
void k_gemm(const int* __restrict__ mem_h,
            const float* __restrict__ entity,
            const float* __restrict__ rel,
            int B)
{
    const int hop  = blockIdx.y;
    const int r    = blockIdx.x;
    const int base = g_off[hop][r];
    const int n    = g_off[hop][r + 1] - base;
    if (n <= 0) return;
    const int ntiles = (n + TM - 1) / TM;

    extern __shared__ char smem[];
    float (*RsT)[RPAD] = (float(*)[RPAD])(smem + ROFF);
    const uint32_t hb[2] = { smem_u32(smem + HOFF),
                             smem_u32(smem + HOFF + HBYTES) };
    int* sslot = (int*)(smem + SOFF);

    const int tid  = threadIdx.x;
    const int ts   = tid >> 3;      // 0..15
    const int ti   = tid & 7;       // 0..7

    const int* __restrict__ mh = mem_h + (size_t)hop * B * NMEM;

    // prefetch helper: gather tile t into buffer bi (skew wraps inside row)
    auto prefetch = [&](int t, int bi) {
        int s = t * TM + tid;
        int slot = -1;
        if (tid < TM) {
            if (s < n) slot = g_slots[hop][base + s];
            sslot[bi * TM + tid] = slot;
            if (slot >= 0) {
                const char* src = (const char*)(entity + (size_t)mh[slot] * D);
                uint32_t rowbase = hb[bi] + tid * HROWB;
                const uint32_t sk = (tid & 7) * 16;
                #pragma unroll
                for (int c = 0; c < 16; ++c)
                    cp16(rowbase + ((sk + c * 16) & 255), src + c * 16);
            }
        }
        cp_commit();
    };

    prefetch(0, 0);

    // stage R transposed (one-time; overlaps with tile-0 gather)
    {
        const float* __restrict__ Rp = rel + (size_t)r * (D * D);
        for (int idx = tid; idx < D * D; idx += 128) {
            int i = idx >> 6, j = idx & 63;
            RsT[j][i] = Rp[idx];
        }
    }

    const float4* R4 = (const float4*)(smem + ROFF);

    for (int t = 0; t < ntiles; ++t) {
        const int bi = t & 1;
        if (t + 1 < ntiles) { prefetch(t + 1, bi ^ 1); cp_wait<1>(); }
        else                { cp_wait<0>(); }
        __syncthreads();   // gather(t) + R (1st iter) visible to all

        const float4* H4 = (const float4*)(smem + HOFF + bi * HBYTES);

        unsigned long long acc2[7][4];
        #pragma unroll
        for (int k = 0; k < 7; ++k)
            #pragma unroll
            for (int p = 0; p < 4; ++p) acc2[k][p] = 0ull;

        #pragma unroll 2
        for (int jq = 0; jq < 16; ++jq) {
            float af[7][4];
            #pragma unroll
            for (int k = 0; k < 7; ++k) {
                // row = ts + 16k (row&7 == ts&7); chunk jq sits at
                // float4 index ((ts&7) + jq) & 15 within the row
                float4 a = H4[(ts + 16 * k) * 16 + (((ts & 7) + jq) & 15)];
                af[k][0] = a.x; af[k][1] = a.y; af[k][2] = a.z; af[k][3] = a.w;
            }
            #pragma unroll
            for (int jj = 0; jj < 4; ++jj) {
                // 8 consecutive b floats -> 4 packed f32x2 lanes (free reinterpret)
                const ulonglong2* bp =
                    (const ulonglong2*)(R4 + (4 * jq + jj) * (RPAD / 4) + ti * 2);
                ulonglong2 t0 = bp[0], t1 = bp[1];
                unsigned long long b2[4] = {t0.x, t0.y, t1.x, t1.y};
                #pragma unroll
                for (int k = 0; k < 7; ++k) {
                    unsigned long long av2 = pack2(af[k][jj]);
                    #pragma unroll
                    for (int p = 0; p < 4; ++p)
                        fma2(acc2[k][p], av2, b2[p]);
                }
            }
        }

        #pragma unroll
        for (int k = 0; k < 7; ++k) {
            int slot = sslot[bi * TM + ts + 16 * k];
            if (slot >= 0) {
                ulonglong2* dst = (ulonglong2*)&g_Y[hop][slot][ti * 8];
                ulonglong2 v0, v1;
                v0.x = acc2[k][0]; v0.y = acc2[k][1];
                v1.x = acc2[k][2]; v1.y = acc2[k][3];
                dst[0] = v0;
                dst[1] = v1;
            }
        }
        __syncthreads();   // done reading buf bi before it is overwritten
    }
}

// ------------------------------------------------------------------
// Fused epilogue: both hops + score. 2 batch elements per block.
__global__ __launch_bounds__(128)
void k_upd(const int* __restrict__ items,
           const int* __restrict__ mem_t,
           const float* __restrict__ entity,
           float* __restrict__ out,
           int B)
{
    const int tid  = threadIdx.x;
    const int sub  = tid >> 6;
    const int t    = tid & 63;
    const int lane = tid & 31;
    const int warp = tid >> 5;
    const int wH   = warp & 1;
    const int b    = blockIdx.x * 2 + sub;

    __shared__ float item_sv[2][D];
    __shared__ float vbuf[2][D];
    __shared__ float lgs[2][NMEM];
    __shared__ float probs[2][NMEM];
    __shared__ float red[4];

    float item = entity[(size_t)items[b] * D + t];
    float y = 0.0f;

    #pragma unroll
    for (int hop = 0; hop < NHOP; ++hop) {
        item_sv[sub][t] = item;
        __syncthreads();

        #pragma unroll
        for (int s = 0; s < 8; ++s) {
            int m = wH * 8 + s;
            const float* Yp = g_Y[hop][b * NMEM + m];
            float v = Yp[lane] * item_sv[sub][lane] +
                      Yp[lane + 32] * item_sv[sub][lane + 32];
            #pragma unroll
            for (int off = 16; off > 0; off >>= 1)
                v += __shfl_xor_sync(0xffffffffu, v, off);
            if (lane == 0) lgs[sub][m] = v;
        }
        __syncthreads();

        if (t < NMEM) {
            float mx = lgs[sub][0];
            #pragma unroll
            for (int k = 1; k < NMEM; ++k) mx = fmaxf(mx, lgs[sub][k]);
            probs[sub][t] = expf(lgs[sub][t] - mx);
        }
        __syncthreads();

        float denom = 0.0f;
        #pragma unroll
        for (int m = 0; m < NMEM; ++m) denom += probs[sub][m];

        const int* tp = mem_t + (size_t)hop * B * NMEM + b * NMEM;
        float o = 0.0f;
        #pragma unroll
        for (int m = 0; m < NMEM; ++m)
            o = fmaf(probs[sub][m], entity[(size_t)tp[m] * D + t], o);
        o /= denom;

        y += o;
        vbuf[sub][t] = item + o;
        __syncthreads();

        float acc = 0.0f;
        #pragma unroll 8
        for (int j = 0; j < D; ++j)
            acc = fmaf(g_Wt[j * D + t], vbuf[sub][j], acc);
        item = acc;
        __syncthreads();
    }

    float p = item * y;
    #pragma unroll
    for (int off = 16; off > 0; off >>= 1)
        p += __shfl_xor_sync(0xffffffffu, p, off);
    if (lane == 0) red[warp] = p;
    __syncthreads();
    if (tid == 0)  out[b] = red[0] + red[1];
    if (tid == 64) out[b] = red[2] + red[3];
}

// ------------------------------------------------------------------
extern "C" void kernel_launch(void* const* d_in, const int* in_sizes, int n_in,
                              void* d_out, int out_size)
{
    const int*   items  = (const int*)  d_in[0];
    const int*   mem_h  = (const int*)  d_in[1];
    const int*   mem_r  = (const int*)  d_in[2];
    const int*   mem_t  = (const int*)  d_in[3];
    const float* entity = (const float*)d_in[4];
    const float* rel    = (const float*)d_in[5];
    const float* W      = (const float*)d_in[6];
    float*       out    = (float*)d_out;

    const int B = in_sizes[0];   // 4096

    static bool attr_set = false;
    if (!attr_set) {
        cudaFuncSetAttribute(k_gemm, cudaFuncAttributeMaxDynamicSharedMemorySize,
                             GEMM_SMEM);
        attr_set = true;
    }

    k_count  <<<dim3(CBLK, NHOP), 256>>>(mem_r, B);
    k_scan   <<<1, 512>>>(W);
    k_scatter<<<dim3(CBLK, NHOP), 256>>>(mem_r, B);
    k_gemm   <<<dim3(NREL, NHOP), 128, GEMM_SMEM>>>(mem_h, entity, rel, B);
    k_upd    <<<B / 2, 128>>>(items, mem_t, entity, out, B);
}

// round 10
// speedup vs baseline: 4.2727x; 1.0583x over previous
#include <cuda_runtime.h>
#include <cstdint>

#define D     64
#define NMEM  16
#define NHOP  2
#define NREL  200
#define BMAX  4096
#define SMAX  (BMAX * NMEM)   // 65536 slots per hop
#define TM    112             // slots per GEMM tile (16 ts-groups x 7)
#define RPAD  68              // RsT row stride (floats)
#define CBLK  32              // histogram/scatter blocks per hop
#define YSPLIT 3              // blocks per bin

// smem layout for k_gemm (bytes) — SINGLE H buffer now
#define ROFF   0
#define RBYTES (D * RPAD * 4)                 // 17408
#define HOFF   RBYTES
#define HROWB  256                            // 64 floats per row (skew wraps in-row)
#define HBYTES (TM * HROWB)                   // 28672
#define SOFF   (HOFF + HBYTES)
#define GEMM_SMEM (SOFF + TM * 4)             // 46592 -> 4 blocks/SM

// ---- persistent scratch (no runtime allocation allowed) ----
__device__ int   g_parthist[NHOP][CBLK][NREL];
__device__ int   g_off   [NHOP][NREL + 1];
__device__ int   g_cursor[NHOP][NREL];
__device__ int   g_slots [NHOP][SMAX];
__device__ float g_Y     [NHOP][SMAX][D];   // Y[slot] = R_{r(slot)} @ h_slot
__device__ float g_Wt    [D * D];           // Wt[j][i] = W[i][j]

// ------------------------------------------------------------------
__device__ __forceinline__ uint32_t smem_u32(const void* p) {
    return (uint32_t)__cvta_generic_to_shared(p);
}
__device__ __forceinline__ void cp16(uint32_t dst, const void* src) {
    asm volatile("cp.async.cg.shared.global [%0], [%1], 16;\n"
                 :: "r"(dst), "l"(src));
}
__device__ __forceinline__ void cp_commit() {
    asm volatile("cp.async.commit_group;\n" ::);
}
template <int N>
__device__ __forceinline__ void cp_wait() {
    asm volatile("cp.async.wait_group %0;\n" :: "n"(N));
}

// packed f32x2 helpers
__device__ __forceinline__ unsigned long long pack2(float v) {
    unsigned long long r;
    asm("mov.b64 %0, {%1, %1};" : "=l"(r) : "f"(v));
    return r;
}
__device__ __forceinline__ void fma2(unsigned long long& d,
                                     unsigned long long a,
                                     unsigned long long b) {
    asm("fma.rn.f32x2 %0, %1, %2, %0;" : "+l"(d) : "l"(a), "l"(b));
}

// ------------------------------------------------------------------
__global__ __launch_bounds__(256)
void k_count(const int* __restrict__ mem_r, int B)
{
    __shared__ int hist[NREL];
    const int hop   = blockIdx.y;
    const int total = B * NMEM;
    const int chunk = (total + CBLK - 1) / CBLK;
    const int start = blockIdx.x * chunk;

    for (int i = threadIdx.x; i < NREL; i += 256) hist[i] = 0;
    __syncthreads();

    const int* src = mem_r + hop * total;
    if ((chunk & 7) == 0 && start + chunk <= total) {
        int base = start + threadIdx.x * 8;
        if (base + 8 <= start + chunk) {
            int4 v0 = *(const int4*)(src + base);
            int4 v1 = *(const int4*)(src + base + 4);
            atomicAdd(&hist[v0.x], 1); atomicAdd(&hist[v0.y], 1);
            atomicAdd(&hist[v0.z], 1); atomicAdd(&hist[v0.w], 1);
            atomicAdd(&hist[v1.x], 1); atomicAdd(&hist[v1.y], 1);
            atomicAdd(&hist[v1.z], 1); atomicAdd(&hist[v1.w], 1);
        }
    } else {
        for (int k = threadIdx.x; k < chunk; k += 256) {
            int idx = start + k;
            if (idx < total) atomicAdd(&hist[src[idx]], 1);
        }
    }
    __syncthreads();

    for (int i = threadIdx.x; i < NREL; i += 256)
        g_parthist[hop][blockIdx.x][i] = hist[i];
}

__global__ __launch_bounds__(512)
void k_scan(const float* __restrict__ W)
{
    __shared__ int cnt[NHOP][NREL];
    const int tid = threadIdx.x;
    if (tid < NHOP * NREL) {
        int hop = tid / NREL, r = tid - hop * NREL;
        int s = 0;
        #pragma unroll 8
        for (int b = 0; b < CBLK; ++b) s += g_parthist[hop][b][r];
        cnt[hop][r] = s;
        g_cursor[hop][r] = 0;
    }
    for (int idx = tid; idx < D * D; idx += 512)
        g_Wt[(idx & (D - 1)) * D + (idx >> 6)] = W[idx];
    __syncthreads();
    if (tid < NHOP) {
        int acc = 0;
        for (int r = 0; r < NREL; ++r) { g_off[tid][r] = acc; acc += cnt[tid][r]; }
        g_off[tid][NREL] = acc;
    }
}

__global__ __launch_bounds__(256)
void k_scatter(const int* __restrict__ mem_r, int B)
{
    __shared__ int hist[NREL];
    __shared__ int base_s[NREL];
    const int hop   = blockIdx.y;
    const int total = B * NMEM;
    const int chunk = (total + CBLK - 1) / CBLK;
    const int start = blockIdx.x * chunk;

    for (int i = threadIdx.x; i < NREL; i += 256) hist[i] = 0;
    __syncthreads();

    const int* src = mem_r + hop * total;
    int rr[8], lrank[8], idx0 = start + threadIdx.x * 8;
    bool vec = ((chunk & 7) == 0) && (idx0 + 8 <= start + chunk) &&
               (start + chunk <= total);
    if (vec) {
        int4 v0 = *(const int4*)(src + idx0);
        int4 v1 = *(const int4*)(src + idx0 + 4);
        rr[0]=v0.x; rr[1]=v0.y; rr[2]=v0.z; rr[3]=v0.w;
        rr[4]=v1.x; rr[5]=v1.y; rr[6]=v1.z; rr[7]=v1.w;
        #pragma unroll
        for (int t = 0; t < 8; ++t) lrank[t] = atomicAdd(&hist[rr[t]], 1);
    } else {
        #pragma unroll
        for (int t = 0; t < 8; ++t) {
            int k = threadIdx.x * 8 + t;
            rr[t] = -1;
            if (k < chunk && start + k < total) {
                rr[t]    = src[start + k];
                lrank[t] = atomicAdd(&hist[rr[t]], 1);
            }
        }
    }
    __syncthreads();

    for (int i = threadIdx.x; i < NREL; i += 256) {
        int c = hist[i];
        base_s[i] = g_off[hop][i] + (c ? atomicAdd(&g_cursor[hop][i], c) : 0);
    }
    __syncthreads();

    #pragma unroll
    for (int t = 0; t < 8; ++t)
        if (vec || rr[t] >= 0)
            g_slots[hop][base_s[rr[t]] + lrank[t]] = idx0 + t;
}

// ------------------------------------------------------------------
// Y[slot] = R @ h_slot. Grid (NREL, YSPLIT, NHOP): each block takes
// tiles by, by+YSPLIT, ... of its bin (usually exactly one tile).
// Single H buffer, 4 blocks/SM, packed f32x2 FMAs, 7x8 micro-tile.
__global__ __launch_bounds__(128, 4)
void k_gemm(const int* __restrict__ mem_h,
            const float* __restrict__ entity,
            const float* __restrict__ rel,
            int B)
{
    const int hop  = blockIdx.z;
    const int r    = blockIdx.x;
    const int base = g_off[hop][r];
    const int n    = g_off[hop][r + 1] - base;
    const int ntiles = (n + TM - 1) / TM;
    if ((int)blockIdx.y >= ntiles) return;

    extern __shared__ char smem[];
    float (*RsT)[RPAD] = (float(*)[RPAD])(smem + ROFF);
    const uint32_t hbase = smem_u32(smem + HOFF);
    int* sslot = (int*)(smem + SOFF);

    const int tid  = threadIdx.x;
    const int ts   = tid >> 3;      // 0..15
    const int ti   = tid & 7;       // 0..7

    const int* __restrict__ mh = mem_h + (size_t)hop * B * NMEM;

    // kick off tile gather for the first tile, then stage R (overlaps)
    int t = blockIdx.y;
    bool first = true;

    for (; t < ntiles; t += YSPLIT) {
        if (!first) __syncthreads();   // previous compute done before overwrite

        // gather tile t into H (in-row 16B skew: chunk c of row at
        // byte ((row&7)*16 + c*16) & 255)
        {
            int s = t * TM + tid;
            if (tid < TM) {
                int slot = (s < n) ? g_slots[hop][base + s] : -1;
                sslot[tid] = slot;
                if (slot >= 0) {
                    const char* src = (const char*)(entity + (size_t)mh[slot] * D);
                    uint32_t rowbase = hbase + tid * HROWB;
                    const uint32_t sk = (tid & 7) * 16;
                    #pragma unroll
                    for (int c = 0; c < 16; ++c)
                        cp16(rowbase + ((sk + c * 16) & 255), src + c * 16);
                }
            }
            cp_commit();
        }

        if (first) {
            // stage R transposed while the gather is in flight
            const float* __restrict__ Rp = rel + (size_t)r * (D * D);
            for (int idx = tid; idx < D * D; idx += 128) {
                int i = idx >> 6, j = idx & 63;
                RsT[j][i] = Rp[idx];
            }
            first = false;
        }

        cp_wait<0>();
        __syncthreads();   // gather + R visible to all

        const float4* R4 = (const float4*)(smem + ROFF);
        const float4* H4 = (const float4*)(smem + HOFF);

        unsigned long long acc2[7][4];
        #pragma unroll
        for (int k = 0; k < 7; ++k)
            #pragma unroll
            for (int p = 0; p < 4; ++p) acc2[k][p] = 0ull;

        #pragma unroll 2
        for (int jq = 0; jq < 16; ++jq) {
            float af[7][4];
            #pragma unroll
            for (int k = 0; k < 7; ++k) {
                // row = ts + 16k (row&7 == ts&7); chunk jq at
                // float4 index ((ts&7) + jq) & 15 within the row
                float4 a = H4[(ts + 16 * k) * 16 + (((ts & 7) + jq) & 15)];
                af[k][0] = a.x; af[k][1] = a.y; af[k][2] = a.z; af[k][3] = a.w;
            }
            #pragma unroll
            for (int jj = 0; jj < 4; ++jj) {
                const ulonglong2* bp =
                    (const ulonglong2*)(R4 + (4 * jq + jj) * (RPAD / 4) + ti * 2);
                ulonglong2 t0 = bp[0], t1 = bp[1];
                unsigned long long b2[4] = {t0.x, t0.y, t1.x, t1.y};
                #pragma unroll
                for (int k = 0; k < 7; ++k) {
                    unsigned long long av2 = pack2(af[k][jj]);
                    #pragma unroll
                    for (int p = 0; p < 4; ++p)
                        fma2(acc2[k][p], av2, b2[p]);
                }
            }
        }

        #pragma unroll
        for (int k = 0; k < 7; ++k) {
            int slot = sslot[ts + 16 * k];
            if (slot >= 0) {
                ulonglong2* dst = (ulonglong2*)&g_Y[hop][slot][ti * 8];
                ulonglong2 v0, v1;
                v0.x = acc2[k][0]; v0.y = acc2[k][1];
                v1.x = acc2[k][2]; v1.y = acc2[k][3];
                dst[0] = v0;
                dst[1] = v1;
            }
        }
    }
}

// ------------------------------------------------------------------
// Fused epilogue: both hops + score. 2 batch elements per block.
__global__ __launch_bounds__(128)
void k_upd(const int* __restrict__ items,
           const int* __restrict__ mem_t,
           const float* __restrict__ entity,
           float* __restrict__ out,
           int B)
{
    const int tid  = threadIdx.x;
    const int sub  = tid >> 6;
    const int t    = tid & 63;
    const int lane = tid & 31;
    const int warp = tid >> 5;
    const int wH   = warp & 1;
    const int b    = blockIdx.x * 2 + sub;

    __shared__ float item_sv[2][D];
    __shared__ float vbuf[2][D];
    __shared__ float lgs[2][NMEM];
    __shared__ float probs[2][NMEM];
    __shared__ float red[4];

    float item = entity[(size_t)items[b] * D + t];
    float y = 0.0f;

    #pragma unroll
    for (int hop = 0; hop < NHOP; ++hop) {
        item_sv[sub][t] = item;
        __syncthreads();

        #pragma unroll
        for (int s = 0; s < 8; ++s) {
            int m = wH * 8 + s;
            const float* Yp = g_Y[hop][b * NMEM + m];
            float v = Yp[lane] * item_sv[sub][lane] +
                      Yp[lane + 32] * item_sv[sub][lane + 32];
            #pragma unroll
            for (int off = 16; off > 0; off >>= 1)
                v += __shfl_xor_sync(0xffffffffu, v, off);
            if (lane == 0) lgs[sub][m] = v;
        }
        __syncthreads();

        if (t < NMEM) {
            float mx = lgs[sub][0];
            #pragma unroll
            for (int k = 1; k < NMEM; ++k) mx = fmaxf(mx, lgs[sub][k]);
            probs[sub][t] = expf(lgs[sub][t] - mx);
        }
        __syncthreads();

        float denom = 0.0f;
        #pragma unroll
        for (int m = 0; m < NMEM; ++m) denom += probs[sub][m];

        const int* tp = mem_t + (size_t)hop * B * NMEM + b * NMEM;
        float o = 0.0f;
        #pragma unroll
        for (int m = 0; m < NMEM; ++m)
            o = fmaf(probs[sub][m], entity[(size_t)tp[m] * D + t], o);
        o /= denom;

        y += o;
        vbuf[sub][t] = item + o;
        __syncthreads();

        float acc = 0.0f;
        #pragma unroll 8
        for (int j = 0; j < D; ++j)
            acc = fmaf(g_Wt[j * D + t], vbuf[sub][j], acc);
        item = acc;
        __syncthreads();
    }

    float p = item * y;
    #pragma unroll
    for (int off = 16; off > 0; off >>= 1)
        p += __shfl_xor_sync(0xffffffffu, p, off);
    if (lane == 0) red[warp] = p;
    __syncthreads();
    if (tid == 0)  out[b] = red[0] + red[1];
    if (tid == 64) out[b] = red[2] + red[3];
}

// ------------------------------------------------------------------
extern "C" void kernel_launch(void* const* d_in, const int* in_sizes, int n_in,
                              void* d_out, int out_size)
{
    const int*   items  = (const int*)  d_in[0];
    const int*   mem_h  = (const int*)  d_in[1];
    const int*   mem_r  = (const int*)  d_in[2];
    const int*   mem_t  = (const int*)  d_in[3];
    const float* entity = (const float*)d_in[4];
    const float* rel    = (const float*)d_in[5];
    const float* W      = (const float*)d_in[6];
    float*       out    = (float*)d_out;

    const int B = in_sizes[0];   // 4096

    static bool attr_set = false;
    if (!attr_set) {
        cudaFuncSetAttribute(k_gemm, cudaFuncAttributeMaxDynamicSharedMemorySize,
                             GEMM_SMEM);
        attr_set = true;
    }

    k_count  <<<dim3(CBLK, NHOP), 256>>>(mem_r, B);
    k_scan   <<<1, 512>>>(W);
    k_scatter<<<dim3(CBLK, NHOP), 256>>>(mem_r, B);
    k_gemm   <<<dim3(NREL, YSPLIT, NHOP), 128, GEMM_SMEM>>>(mem_h, entity, rel, B);
    k_upd    <<<B / 2, 128>>>(items, mem_t, entity, out, B);
}